// round 11
// baseline (speedup 1.0000x reference)
#include <cuda_runtime.h>
#include <math.h>

// TemplatePointwiseAttention fused kernel, fp32, warp-per-4-pairs.
// Shapes: B=1, T=4, L=384, c_z=128, c_t=64, H=4, C=16.
//
// R3 dataflow (305us best) with pair-in-lane multicast layout in the three
// broadcast-heavy GEMV stages (q / o / out): lane = (p=lane/8, g=lane%8);
// activation reads become 4-address LDS.128 multicasts (1 wf serves warp),
// weights become LDG.128 (1 wf each). Cuts ~100 L1 wavefronts/pair.
// r / u / LN / softmax stages identical to R3.

namespace {
constexpr int L_ = 384;
constexpr int NPAIR = L_ * L_;        // 147456
constexpr int NP = 4;                 // pairs per warp iteration
constexpr int NB = NPAIR / NP;        // 36864
constexpr int WARPS = 4;
constexpr int NTHREADS = WARPS * 32;  // 128
constexpr int GRID = 152 * 4;         // 608

// per-pair scratch (floats):
//   [0..271]   r_s  (4 x 68)  -> reused as u after softmax
//   [272..543] tn_s (4 x 68)  -> first 128 floats overlay zn
//   [544..607] q_s  (64)
//   [608..623] at_s (16)
//   [624..687] o_s  (64)
// SCR_P = 696 (== 24 mod 32 banks) so the 4 pair bases hit distinct banks
// in the multicast loads (p*24 mod 32 = 0,24,16,8).
constexpr int SCR_P = 696;
constexpr int SCR_W = NP * SCR_P;                    // 2784 per warp
constexpr int SMEM_FLOATS = WARPS * SCR_W;           // 11136 -> 44544 B

__device__ float g_WkT[64 * 64];   // WkT[c][m] = Wk[m][c]

__device__ __forceinline__ float dot4(float4 a, float4 b) {
    return fmaf(a.x, b.x, fmaf(a.y, b.y, fmaf(a.z, b.z, a.w * b.w)));
}
__device__ __forceinline__ float4 fma4(float s, float4 w, float4 a) {
    a.x = fmaf(s, w.x, a.x); a.y = fmaf(s, w.y, a.y);
    a.z = fmaf(s, w.z, a.z); a.w = fmaf(s, w.w, a.w);
    return a;
}
__device__ __forceinline__ float4 ldcs4(const float* p) { return __ldcs((const float4*)p); }
__device__ __forceinline__ float2 ldcs2(const float* p) { return __ldcs((const float2*)p); }
} // namespace

__global__ void tpa_prep(const float* __restrict__ Wk) {
    int idx = blockIdx.x * blockDim.x + threadIdx.x;
    if (idx < 4096) {
        int m = idx >> 6, c = idx & 63;
        g_WkT[c * 64 + m] = Wk[idx];
    }
}

__global__ __launch_bounds__(NTHREADS, 4) void tpa_fused(
    const float* __restrict__ tin,   // [4,384,384,64]
    const float* __restrict__ zin,   // [384,384,128]
    const float* __restrict__ mask,  // [4,384]
    const float* __restrict__ zg_, const float* __restrict__ zb_,
    const float* __restrict__ tg_, const float* __restrict__ tb_,
    const float* __restrict__ Wq,    // [128,64]
    const float* __restrict__ Wv,    // [64,64]
    const float* __restrict__ Wo,    // [64,128]
    const float* __restrict__ bo,    // [128]
    float* __restrict__ out)         // [384,384,128]
{
    __shared__ float sm[SMEM_FLOATS];
    const int tid  = threadIdx.x;
    const int warp = tid >> 5, lane = tid & 31;
    float* scr = sm + warp * SCR_W;

    const float4 zg = *(const float4*)(zg_ + lane * 4);
    const float4 zb = *(const float4*)(zb_ + lane * 4);
    const float2 tg = *(const float2*)(tg_ + lane * 2);
    const float2 tb = *(const float2*)(tb_ + lane * 2);

    // pair-in-lane decomposition for q / o / out stages
    const int pl = lane >> 3;        // pair owned (0..3)
    const int g  = lane & 7;         // output octet (0..7)
    const int hg = g >> 1;           // head for n = 8g..8g+7 (o-stage)
    const float4 bo0 = *(const float4*)(bo + 16 * g);
    const float4 bo1 = *(const float4*)(bo + 16 * g + 4);
    const float4 bo2 = *(const float4*)(bo + 16 * g + 8);
    const float4 bo3 = *(const float4*)(bo + 16 * g + 12);

    const int idx16 = lane & 15;
    const int half  = lane >> 4;     // m-half for logit partial
    const int t_of  = idx16 >> 2;    // template idx (logits lane)
    const int h_of  = idx16 & 3;     // head idx (logits lane)

    const int gw = blockIdx.x * WARPS + warp;
    const int nw = GRID * WARPS;

    for (int b = gw; b < NB; b += nw) {
        const int p0 = b * NP;
        const int i  = p0 / L_;          // all 4 pairs share row i
        const int j0 = p0 - i * L_;

        // ---- z loads + LN (per pair); zn overlays tn region ----
        #pragma unroll
        for (int k = 0; k < NP; k++) {
            float4 zv = ldcs4(zin + (size_t)(p0 + k) * 128 + lane * 4);
            float s  = zv.x + zv.y + zv.z + zv.w;
            float ss = zv.x * zv.x + zv.y * zv.y + zv.z * zv.z + zv.w * zv.w;
            #pragma unroll
            for (int o = 16; o > 0; o >>= 1) {
                s  += __shfl_xor_sync(0xffffffffu, s,  o);
                ss += __shfl_xor_sync(0xffffffffu, ss, o);
            }
            float mu   = s * (1.0f / 128.0f);
            float rstd = rsqrtf(fmaf(ss, 1.0f / 128.0f, -mu * mu) + 1e-5f);
            float4 znv;
            znv.x = (zv.x - mu) * rstd * zg.x + zb.x;
            znv.y = (zv.y - mu) * rstd * zg.y + zb.y;
            znv.z = (zv.z - mu) * rstd * zg.z + zb.z;
            znv.w = (zv.w - mu) * rstd * zg.w + zb.w;
            *(float4*)(scr + k * SCR_P + 272 + lane * 4) = znv;
        }
        __syncwarp();

        // ---- prefetch t (streaming; consumed after q/r compute) ----
        float2 tv[NP][4];
        #pragma unroll
        for (int k = 0; k < NP; k++)
            #pragma unroll
            for (int t = 0; t < 4; t++)
                tv[k][t] = ldcs2(tin + ((size_t)(t * L_ + i) * L_ + (j0 + k)) * 64 + lane * 2);

        // ---- q[n] = zn . Wq[:,n] (pair-in-lane: lane owns pair pl, n=8g..8g+7) ----
        {
            float4 qa = make_float4(0.f, 0.f, 0.f, 0.f);
            float4 qb = make_float4(0.f, 0.f, 0.f, 0.f);
            const float* znp = scr + pl * SCR_P + 272;
            const float* wq  = Wq + 8 * g;
            #pragma unroll 4
            for (int m = 0; m < 128; m += 4) {
                float4 z4 = *(const float4*)(znp + m);   // 4-addr multicast, 1 wf
                const float* w = wq + m * 64;
                float4 w0a = *(const float4*)(w);        float4 w0b = *(const float4*)(w + 4);
                float4 w1a = *(const float4*)(w + 64);   float4 w1b = *(const float4*)(w + 68);
                float4 w2a = *(const float4*)(w + 128);  float4 w2b = *(const float4*)(w + 132);
                float4 w3a = *(const float4*)(w + 192);  float4 w3b = *(const float4*)(w + 196);
                qa = fma4(z4.x, w0a, qa); qb = fma4(z4.x, w0b, qb);
                qa = fma4(z4.y, w1a, qa); qb = fma4(z4.y, w1b, qb);
                qa = fma4(z4.z, w2a, qa); qb = fma4(z4.z, w2b, qb);
                qa = fma4(z4.w, w3a, qa); qb = fma4(z4.w, w3b, qb);
            }
            *(float4*)(scr + pl * SCR_P + 544 + 8 * g)     = qa;
            *(float4*)(scr + pl * SCR_P + 544 + 8 * g + 4) = qb;
        }
        __syncwarp();

        // ---- r[h][m] = sum_c q[h*16+c]*WkT[h*16+c][m]; lane owns m=2l,2l+1 ----
        #pragma unroll
        for (int h = 0; h < 4; h++) {
            float2 racc[NP];
            #pragma unroll
            for (int k = 0; k < NP; k++) racc[k] = make_float2(0.f, 0.f);
            #pragma unroll
            for (int cc = 0; cc < 16; cc += 4) {
                const float* wk = g_WkT + (h * 16 + cc) * 64 + 2 * lane;
                float2 w0 = *(const float2*)(wk);
                float2 w1 = *(const float2*)(wk + 64);
                float2 w2 = *(const float2*)(wk + 128);
                float2 w3 = *(const float2*)(wk + 192);
                #pragma unroll
                for (int k = 0; k < NP; k++) {
                    float4 qv = *(const float4*)(scr + k * SCR_P + 544 + h * 16 + cc);
                    racc[k].x = fmaf(qv.x, w0.x, fmaf(qv.y, w1.x,
                                fmaf(qv.z, w2.x, fmaf(qv.w, w3.x, racc[k].x))));
                    racc[k].y = fmaf(qv.x, w0.y, fmaf(qv.y, w1.y,
                                fmaf(qv.z, w2.y, fmaf(qv.w, w3.y, racc[k].y))));
                }
            }
            #pragma unroll
            for (int k = 0; k < NP; k++)
                *(float2*)(scr + k * SCR_P + h * 68 + 2 * lane) = racc[k];
        }
        __syncwarp();   // q/zn reads done; tn may overwrite zn region

        // ---- t layernorms (lane owns m = 2*lane, 2*lane+1) ----
        #pragma unroll
        for (int k = 0; k < NP; k++)
            #pragma unroll
            for (int t = 0; t < 4; t++) {
                float2 v = tv[k][t];
                float s  = v.x + v.y;
                float ss = v.x * v.x + v.y * v.y;
                #pragma unroll
                for (int o = 16; o > 0; o >>= 1) {
                    s  += __shfl_xor_sync(0xffffffffu, s,  o);
                    ss += __shfl_xor_sync(0xffffffffu, ss, o);
                }
                float mu   = s * (1.0f / 64.0f);
                float rstd = rsqrtf(fmaf(ss, 1.0f / 64.0f, -mu * mu) + 1e-5f);
                float2 tnv;
                tnv.x = (v.x - mu) * rstd * tg.x + tb.x;
                tnv.y = (v.y - mu) * rstd * tg.y + tb.y;
                *(float2*)(scr + k * SCR_P + 272 + t * 68 + lane * 2) = tnv;
            }
        __syncwarp();

        // ---- logits + masked softmax over t (per pair) ----
        const float pm_i = mask[t_of * L_ + i];
        #pragma unroll
        for (int k = 0; k < NP; k++) {
            const float* tnp = scr + k * SCR_P + 272 + t_of * 68 + half * 32;
            const float* rp  = scr + k * SCR_P + h_of * 68 + half * 32;
            float acc = 0.f;
            #pragma unroll
            for (int s4 = 0; s4 < 32; s4 += 4)
                acc += dot4(*(const float4*)(tnp + s4), *(const float4*)(rp + s4));
            acc += __shfl_xor_sync(0xffffffffu, acc, 16);
            float logit = acc * 0.25f;

            float pm = pm_i * mask[t_of * L_ + j0 + k];
            logit = (pm == 0.0f) ? -1e9f : logit;

            float mx = fmaxf(logit, __shfl_xor_sync(0xffffffffu, logit, 4));
            mx = fmaxf(mx, __shfl_xor_sync(0xffffffffu, mx, 8));
            float e = __expf(logit - mx);
            float den = e + __shfl_xor_sync(0xffffffffu, e, 4);
            den += __shfl_xor_sync(0xffffffffu, den, 8);
            float attn = __fdividef(e, den) * pm;
            float s2 = attn + __shfl_xor_sync(0xffffffffu, attn, 4);
            s2 += __shfl_xor_sync(0xffffffffu, s2, 8);
            attn = __fdividef(attn, fmaxf(s2, 1e-8f));
            scr[k * SCR_P + 608 + t_of * 4 + h_of] = attn;  // l and l^16 same val
        }
        __syncwarp();

        // ---- u[h][m] = sum_t attn[t,h]*tn[t][m]; lane owns m=lane,lane+32 ----
        #pragma unroll
        for (int k = 0; k < NP; k++) {
            float* pk = scr + k * SCR_P;
            float u0[4] = {0.f, 0.f, 0.f, 0.f};
            float u1[4] = {0.f, 0.f, 0.f, 0.f};
            #pragma unroll
            for (int t = 0; t < 4; t++) {
                float  a0 = pk[272 + t * 68 + lane];
                float  a1 = pk[272 + t * 68 + lane + 32];
                float4 av = *(const float4*)(pk + 608 + t * 4);   // attn[t][0..3]
                u0[0] = fmaf(av.x, a0, u0[0]); u1[0] = fmaf(av.x, a1, u1[0]);
                u0[1] = fmaf(av.y, a0, u0[1]); u1[1] = fmaf(av.y, a1, u1[1]);
                u0[2] = fmaf(av.z, a0, u0[2]); u1[2] = fmaf(av.z, a1, u1[2]);
                u0[3] = fmaf(av.w, a0, u0[3]); u1[3] = fmaf(av.w, a1, u1[3]);
            }
            #pragma unroll
            for (int h = 0; h < 4; h++) {
                pk[h * 68 + lane]      = u0[h];   // overwrite r with u
                pk[h * 68 + lane + 32] = u1[h];
            }
        }
        __syncwarp();

        // ---- o[n] = u[h(n)] . Wv[:,n] (pair-in-lane: pair pl, n=8g..8g+7, h=g/2) ----
        {
            float4 oa = make_float4(0.f, 0.f, 0.f, 0.f);
            float4 ob = make_float4(0.f, 0.f, 0.f, 0.f);
            const float* up = scr + pl * SCR_P + hg * 68;
            const float* wv = Wv + 8 * g;
            #pragma unroll 4
            for (int m = 0; m < 64; m += 4) {
                float4 u4 = *(const float4*)(up + m);    // 16-addr multicast
                const float* w = wv + m * 64;
                float4 w0a = *(const float4*)(w);        float4 w0b = *(const float4*)(w + 4);
                float4 w1a = *(const float4*)(w + 64);   float4 w1b = *(const float4*)(w + 68);
                float4 w2a = *(const float4*)(w + 128);  float4 w2b = *(const float4*)(w + 132);
                float4 w3a = *(const float4*)(w + 192);  float4 w3b = *(const float4*)(w + 196);
                oa = fma4(u4.x, w0a, oa); ob = fma4(u4.x, w0b, ob);
                oa = fma4(u4.y, w1a, oa); ob = fma4(u4.y, w1b, ob);
                oa = fma4(u4.z, w2a, oa); ob = fma4(u4.z, w2b, ob);
                oa = fma4(u4.w, w3a, oa); ob = fma4(u4.w, w3b, ob);
            }
            *(float4*)(scr + pl * SCR_P + 624 + 8 * g)     = oa;
            *(float4*)(scr + pl * SCR_P + 624 + 8 * g + 4) = ob;
        }
        __syncwarp();

        // ---- out[j'] = o . Wo[:,j'] + bo (pair-in-lane: pair pl, j'=16g..16g+15) ----
        {
            float4 a0 = bo0, a1 = bo1, a2 = bo2, a3 = bo3;
            const float* op = scr + pl * SCR_P + 624;
            const float* wo = Wo + 16 * g;
            #pragma unroll 4
            for (int n = 0; n < 64; n += 2) {
                float2 o2 = *(const float2*)(op + n);    // 4-addr multicast, 1 wf
                const float* w = wo + n * 128;
                float4 w00 = *(const float4*)(w);        float4 w01 = *(const float4*)(w + 4);
                float4 w02 = *(const float4*)(w + 8);    float4 w03 = *(const float4*)(w + 12);
                float4 w10 = *(const float4*)(w + 128);  float4 w11 = *(const float4*)(w + 132);
                float4 w12 = *(const float4*)(w + 136);  float4 w13 = *(const float4*)(w + 140);
                a0 = fma4(o2.x, w00, a0); a1 = fma4(o2.x, w01, a1);
                a2 = fma4(o2.x, w02, a2); a3 = fma4(o2.x, w03, a3);
                a0 = fma4(o2.y, w10, a0); a1 = fma4(o2.y, w11, a1);
                a2 = fma4(o2.y, w12, a2); a3 = fma4(o2.y, w13, a3);
            }
            float* dst = out + (size_t)(p0 + pl) * 128 + 16 * g;
            __stcs((float4*)(dst),      a0);
            __stcs((float4*)(dst + 4),  a1);
            __stcs((float4*)(dst + 8),  a2);
            __stcs((float4*)(dst + 12), a3);
        }
        __syncwarp();   // scratch reuse barrier before next block
    }
}

extern "C" void kernel_launch(void* const* d_in, const int* in_sizes, int n_in,
                              void* d_out, int out_size) {
    (void)in_sizes; (void)n_in; (void)out_size;
    tpa_prep<<<16, 256>>>((const float*)d_in[8]);   // Wk
    tpa_fused<<<GRID, NTHREADS>>>(
        (const float*)d_in[0],  // t
        (const float*)d_in[1],  // z
        (const float*)d_in[2],  // template_mask
        (const float*)d_in[3],  // z_ln_g
        (const float*)d_in[4],  // z_ln_b
        (const float*)d_in[5],  // t_ln_g
        (const float*)d_in[6],  // t_ln_b
        (const float*)d_in[7],  // Wq
        (const float*)d_in[9],  // Wv
        (const float*)d_in[10], // Wo
        (const float*)d_in[11], // bo
        (float*)d_out);
}

// round 13
// speedup vs baseline: 3.3673x; 3.3673x over previous
#include <cuda_runtime.h>
#include <math.h>

// TemplatePointwiseAttention fused kernel, fp32, warp-per-4-pairs.
// Shapes: B=1, T=4, L=384, c_z=128, c_t=64, H=4, C=16.
//
// R3 dataflow/weight-access (305us) with scratch-wavefront removal:
//  - r and tn live in REGISTERS (lane owns m=lane, lane+32); logits computed
//    as 32 FMA/lane partials + 16-shfl butterfly reduction (was 64 LDS wf).
//  - u computed in registers (attn via 4 bcast LDS.128), stored once for o.
//  - q/o/out broadcast reads widened to LDS.128 feeding 4 weight rows.
// Weight LDG patterns identical to R3 (contiguous per-lane columns).

namespace {
constexpr int L_ = 384;
constexpr int NPAIR = L_ * L_;        // 147456
constexpr int NP = 4;                 // pairs per warp iteration
constexpr int NB = NPAIR / NP;        // 36864
constexpr int WARPS = 4;
constexpr int NTHREADS = WARPS * 32;  // 128
constexpr int GRID = 152 * 4;         // 608

// per-pair scratch (floats):
//   [0..271]   u_s  (4 x 68)   (zn[128] overlays before u is written)
//   [272..335] q_s  (64)
//   [336..351] at_s (16)
//   [352..415] o_s  (64)
constexpr int U_OFF = 0;
constexpr int Q_OFF = 272;
constexpr int A_OFF = 336;
constexpr int O_OFF = 352;
constexpr int SCR_P = 420;
constexpr int SCR_W = NP * SCR_P;                    // 1680 per warp
constexpr int SMEM_FLOATS = WARPS * SCR_W;           // 6720 -> 26880 B

__device__ float g_WkT[64 * 64];   // WkT[c][m] = Wk[m][c]

__device__ __forceinline__ float4 fma4(float s, float4 w, float4 a) {
    a.x = fmaf(s, w.x, a.x); a.y = fmaf(s, w.y, a.y);
    a.z = fmaf(s, w.z, a.z); a.w = fmaf(s, w.w, a.w);
    return a;
}
__device__ __forceinline__ float4 ldcs4(const float* p) { return __ldcs((const float4*)p); }
} // namespace

__global__ void tpa_prep(const float* __restrict__ Wk) {
    int idx = blockIdx.x * blockDim.x + threadIdx.x;
    if (idx < 4096) {
        int m = idx >> 6, c = idx & 63;
        g_WkT[c * 64 + m] = Wk[idx];
    }
}

__global__ __launch_bounds__(NTHREADS, 4) void tpa_fused(
    const float* __restrict__ tin,   // [4,384,384,64]
    const float* __restrict__ zin,   // [384,384,128]
    const float* __restrict__ mask,  // [4,384]
    const float* __restrict__ zg_, const float* __restrict__ zb_,
    const float* __restrict__ tg_, const float* __restrict__ tb_,
    const float* __restrict__ Wq,    // [128,64]
    const float* __restrict__ Wv,    // [64,64]
    const float* __restrict__ Wo,    // [64,128]
    const float* __restrict__ bo,    // [128]
    float* __restrict__ out)         // [384,384,128]
{
    __shared__ float sm[SMEM_FLOATS];
    const int tid  = threadIdx.x;
    const int warp = tid >> 5, lane = tid & 31;
    float* scr = sm + warp * SCR_W;

    const float4 zg = *(const float4*)(zg_ + lane * 4);
    const float4 zb = *(const float4*)(zb_ + lane * 4);
    const float tgA = tg_[lane], tgB = tg_[lane + 32];
    const float tbA = tb_[lane], tbB = tb_[lane + 32];
    const float4 bo4 = *(const float4*)(bo + lane * 4);

    const int idx16 = lane & 15;
    const int t_of  = idx16 >> 2;    // template idx for this lane's logit
    const int h_of  = idx16 & 3;     // head idx
    const int h_o   = lane >> 3;     // head owned in o-stage (n = 2*lane)
    const bool l3 = (lane >> 3) & 1, l2 = (lane >> 2) & 1;
    const bool l1 = (lane >> 1) & 1, l0 = lane & 1;

    const int gw = blockIdx.x * WARPS + warp;
    const int nw = GRID * WARPS;

    for (int b = gw; b < NB; b += nw) {
        const int p0 = b * NP;
        const int i  = p0 / L_;          // all 4 pairs share row i
        const int j0 = p0 - i * L_;

        // ---- z loads + LN; zn stored into U region (u written later) ----
        #pragma unroll
        for (int k = 0; k < NP; k++) {
            float4 zv = ldcs4(zin + (size_t)(p0 + k) * 128 + lane * 4);
            float s  = zv.x + zv.y + zv.z + zv.w;
            float ss = zv.x * zv.x + zv.y * zv.y + zv.z * zv.z + zv.w * zv.w;
            #pragma unroll
            for (int o = 16; o > 0; o >>= 1) {
                s  += __shfl_xor_sync(0xffffffffu, s,  o);
                ss += __shfl_xor_sync(0xffffffffu, ss, o);
            }
            float mu   = s * (1.0f / 128.0f);
            float rstd = rsqrtf(fmaf(ss, 1.0f / 128.0f, -mu * mu) + 1e-5f);
            float4 znv;
            znv.x = (zv.x - mu) * rstd * zg.x + zb.x;
            znv.y = (zv.y - mu) * rstd * zg.y + zb.y;
            znv.z = (zv.z - mu) * rstd * zg.z + zb.z;
            znv.w = (zv.w - mu) * rstd * zg.w + zb.w;
            *(float4*)(scr + k * SCR_P + U_OFF + lane * 4) = znv;
        }
        __syncwarp();

        // ---- prefetch t into registers (lane owns m=lane and m=lane+32) ----
        float tn0[NP][4], tn1[NP][4];
        #pragma unroll
        for (int k = 0; k < NP; k++)
            #pragma unroll
            for (int t = 0; t < 4; t++) {
                const float* tp = tin + ((size_t)(t * L_ + i) * L_ + (j0 + k)) * 64;
                tn0[k][t] = __ldcs(tp + lane);
                tn1[k][t] = __ldcs(tp + lane + 32);
            }

        // ---- q[n] = zn . Wq[:,n]; lane owns n=2l,2l+1; LDS.128 bcast / 4 rows ----
        {
            float2 qacc[NP];
            #pragma unroll
            for (int k = 0; k < NP; k++) qacc[k] = make_float2(0.f, 0.f);
            const float* wq = Wq + 2 * lane;
            #pragma unroll 4
            for (int m = 0; m < 128; m += 4) {
                const float* w = wq + m * 64;
                float2 w0 = *(const float2*)(w);
                float2 w1 = *(const float2*)(w + 64);
                float2 w2 = *(const float2*)(w + 128);
                float2 w3 = *(const float2*)(w + 192);
                #pragma unroll
                for (int k = 0; k < NP; k++) {
                    float4 z4 = *(const float4*)(scr + k * SCR_P + U_OFF + m);  // bcast
                    qacc[k].x = fmaf(z4.x, w0.x, fmaf(z4.y, w1.x,
                                fmaf(z4.z, w2.x, fmaf(z4.w, w3.x, qacc[k].x))));
                    qacc[k].y = fmaf(z4.x, w0.y, fmaf(z4.y, w1.y,
                                fmaf(z4.z, w2.y, fmaf(z4.w, w3.y, qacc[k].y))));
                }
            }
            #pragma unroll
            for (int k = 0; k < NP; k++)
                *(float2*)(scr + k * SCR_P + Q_OFF + 2 * lane) = qacc[k];
        }
        __syncwarp();

        // ---- r[h][m] in REGISTERS: lane owns m=lane (r0), m=lane+32 (r1) ----
        float r0[NP][4], r1[NP][4];
        #pragma unroll
        for (int k = 0; k < NP; k++)
            #pragma unroll
            for (int h = 0; h < 4; h++) { r0[k][h] = 0.f; r1[k][h] = 0.f; }
        #pragma unroll
        for (int h = 0; h < 4; h++) {
            #pragma unroll
            for (int cc = 0; cc < 16; cc += 4) {
                const float* wk = g_WkT + (h * 16 + cc) * 64;
                float w0l = wk[lane],        w0h = wk[lane + 32];
                float w1l = wk[64 + lane],   w1h = wk[64 + lane + 32];
                float w2l = wk[128 + lane],  w2h = wk[128 + lane + 32];
                float w3l = wk[192 + lane],  w3h = wk[192 + lane + 32];
                #pragma unroll
                for (int k = 0; k < NP; k++) {
                    float4 q4 = *(const float4*)(scr + k * SCR_P + Q_OFF + h * 16 + cc);
                    r0[k][h] = fmaf(q4.x, w0l, fmaf(q4.y, w1l,
                               fmaf(q4.z, w2l, fmaf(q4.w, w3l, r0[k][h]))));
                    r1[k][h] = fmaf(q4.x, w0h, fmaf(q4.y, w1h,
                               fmaf(q4.z, w2h, fmaf(q4.w, w3h, r1[k][h]))));
                }
            }
        }

        // ---- t layernorms in registers (same lane-owned m layout) ----
        #pragma unroll
        for (int k = 0; k < NP; k++)
            #pragma unroll
            for (int t = 0; t < 4; t++) {
                float a = tn0[k][t], c2 = tn1[k][t];
                float s  = a + c2;
                float ss = a * a + c2 * c2;
                #pragma unroll
                for (int o = 16; o > 0; o >>= 1) {
                    s  += __shfl_xor_sync(0xffffffffu, s,  o);
                    ss += __shfl_xor_sync(0xffffffffu, ss, o);
                }
                float mu   = s * (1.0f / 64.0f);
                float rstd = rsqrtf(fmaf(ss, 1.0f / 64.0f, -mu * mu) + 1e-5f);
                tn0[k][t] = (a  - mu) * rstd * tgA + tbA;
                tn1[k][t] = (c2 - mu) * rstd * tgB + tbB;
            }

        // ---- logits: register partials + butterfly shfl reduction; softmax ----
        const float pm_i = mask[t_of * L_ + i];
        #pragma unroll
        for (int k = 0; k < NP; k++) {
            float P[16];
            #pragma unroll
            for (int t = 0; t < 4; t++)
                #pragma unroll
                for (int h = 0; h < 4; h++)
                    P[t * 4 + h] = fmaf(tn0[k][t], r0[k][h], tn1[k][t] * r1[k][h]);

            // reduce 16 values across 32 lanes -> lane idx16 holds v=idx16
            float Q[8];
            #pragma unroll
            for (int j = 0; j < 8; j++) {
                float snd = l3 ? P[j] : P[j + 8];
                float kp  = l3 ? P[j + 8] : P[j];
                Q[j] = kp + __shfl_xor_sync(0xffffffffu, snd, 8);
            }
            float R4[4];
            #pragma unroll
            for (int j = 0; j < 4; j++) {
                float snd = l2 ? Q[j] : Q[j + 4];
                float kp  = l2 ? Q[j + 4] : Q[j];
                R4[j] = kp + __shfl_xor_sync(0xffffffffu, snd, 4);
            }
            float S2[2];
            #pragma unroll
            for (int j = 0; j < 2; j++) {
                float snd = l1 ? R4[j] : R4[j + 2];
                float kp  = l1 ? R4[j + 2] : R4[j];
                S2[j] = kp + __shfl_xor_sync(0xffffffffu, snd, 2);
            }
            float snd = l0 ? S2[0] : S2[1];
            float kp  = l0 ? S2[1] : S2[0];
            float T = kp + __shfl_xor_sync(0xffffffffu, snd, 1);
            T += __shfl_xor_sync(0xffffffffu, T, 16);   // fold lane halves

            float logit = T * 0.25f;                    // 1/sqrt(C)
            float pm = pm_i * mask[t_of * L_ + j0 + k];
            logit = (pm == 0.0f) ? -1e9f : logit;

            // softmax over t: xor 4 flips t bit0, xor 8 flips t bit1
            float mx = fmaxf(logit, __shfl_xor_sync(0xffffffffu, logit, 4));
            mx = fmaxf(mx, __shfl_xor_sync(0xffffffffu, mx, 8));
            float e = __expf(logit - mx);
            float den = e + __shfl_xor_sync(0xffffffffu, e, 4);
            den += __shfl_xor_sync(0xffffffffu, den, 8);
            float attn = __fdividef(e, den) * pm;
            float s2 = attn + __shfl_xor_sync(0xffffffffu, attn, 4);
            s2 += __shfl_xor_sync(0xffffffffu, s2, 8);
            attn = __fdividef(attn, fmaxf(s2, 1e-8f));
            scr[k * SCR_P + A_OFF + t_of * 4 + h_of] = attn;  // halves write same
        }
        __syncwarp();

        // ---- u[h][m] in registers (attn via bcast), store once for o-stage ----
        #pragma unroll
        for (int k = 0; k < NP; k++) {
            float u00 = 0.f, u01 = 0.f, u02 = 0.f, u03 = 0.f;
            float u10 = 0.f, u11 = 0.f, u12 = 0.f, u13 = 0.f;
            #pragma unroll
            for (int t = 0; t < 4; t++) {
                float4 av = *(const float4*)(scr + k * SCR_P + A_OFF + t * 4); // bcast
                float a = tn0[k][t], c2 = tn1[k][t];
                u00 = fmaf(av.x, a, u00); u10 = fmaf(av.x, c2, u10);
                u01 = fmaf(av.y, a, u01); u11 = fmaf(av.y, c2, u11);
                u02 = fmaf(av.z, a, u02); u12 = fmaf(av.z, c2, u12);
                u03 = fmaf(av.w, a, u03); u13 = fmaf(av.w, c2, u13);
            }
            float* pk = scr + k * SCR_P + U_OFF;
            pk[lane]            = u00;  pk[lane + 32]       = u10;
            pk[68 + lane]       = u01;  pk[68 + lane + 32]  = u11;
            pk[136 + lane]      = u02;  pk[136 + lane + 32] = u12;
            pk[204 + lane]      = u03;  pk[204 + lane + 32] = u13;
        }
        __syncwarp();

        // ---- o[n] = u[h(n)] . Wv[:,n]; lane owns n=2l,2l+1; bcast LDS.128 ----
        {
            float2 oacc[NP];
            #pragma unroll
            for (int k = 0; k < NP; k++) oacc[k] = make_float2(0.f, 0.f);
            const float* wv = Wv + 2 * lane;
            #pragma unroll 4
            for (int m = 0; m < 64; m += 4) {
                const float* w = wv + m * 64;
                float2 w0 = *(const float2*)(w);
                float2 w1 = *(const float2*)(w + 64);
                float2 w2 = *(const float2*)(w + 128);
                float2 w3 = *(const float2*)(w + 192);
                #pragma unroll
                for (int k = 0; k < NP; k++) {
                    float4 u4 = *(const float4*)(scr + k * SCR_P + U_OFF + h_o * 68 + m);
                    oacc[k].x = fmaf(u4.x, w0.x, fmaf(u4.y, w1.x,
                                fmaf(u4.z, w2.x, fmaf(u4.w, w3.x, oacc[k].x))));
                    oacc[k].y = fmaf(u4.x, w0.y, fmaf(u4.y, w1.y,
                                fmaf(u4.z, w2.y, fmaf(u4.w, w3.y, oacc[k].y))));
                }
            }
            #pragma unroll
            for (int k = 0; k < NP; k++)
                *(float2*)(scr + k * SCR_P + O_OFF + 2 * lane) = oacc[k];
        }
        __syncwarp();

        // ---- out[j'] = o . Wo[:,j'] + bo; lane owns j'=4l..4l+3; bcast LDS.128 ----
        {
            float4 acc[NP];
            #pragma unroll
            for (int k = 0; k < NP; k++) acc[k] = bo4;
            const float* wo = Wo + 4 * lane;
            #pragma unroll 4
            for (int n = 0; n < 64; n += 4) {
                const float* w = wo + n * 128;
                float4 w0 = *(const float4*)(w);
                float4 w1 = *(const float4*)(w + 128);
                float4 w2 = *(const float4*)(w + 256);
                float4 w3 = *(const float4*)(w + 384);
                #pragma unroll
                for (int k = 0; k < NP; k++) {
                    float4 o4 = *(const float4*)(scr + k * SCR_P + O_OFF + n);  // bcast
                    acc[k] = fma4(o4.x, w0, acc[k]);
                    acc[k] = fma4(o4.y, w1, acc[k]);
                    acc[k] = fma4(o4.z, w2, acc[k]);
                    acc[k] = fma4(o4.w, w3, acc[k]);
                }
            }
            #pragma unroll
            for (int k = 0; k < NP; k++)
                __stcs((float4*)(out + (size_t)(p0 + k) * 128 + 4 * lane), acc[k]);
        }
        __syncwarp();   // scratch reuse barrier before next block
    }
}

extern "C" void kernel_launch(void* const* d_in, const int* in_sizes, int n_in,
                              void* d_out, int out_size) {
    (void)in_sizes; (void)n_in; (void)out_size;
    tpa_prep<<<16, 256>>>((const float*)d_in[8]);   // Wk
    tpa_fused<<<GRID, NTHREADS>>>(
        (const float*)d_in[0],  // t
        (const float*)d_in[1],  // z
        (const float*)d_in[2],  // template_mask
        (const float*)d_in[3],  // z_ln_g
        (const float*)d_in[4],  // z_ln_b
        (const float*)d_in[5],  // t_ln_g
        (const float*)d_in[6],  // t_ln_b
        (const float*)d_in[7],  // Wq
        (const float*)d_in[9],  // Wv
        (const float*)d_in[10], // Wo
        (const float*)d_in[11], // bo
        (float*)d_out);
}